// round 1
// baseline (speedup 1.0000x reference)
#include <cuda_runtime.h>
#include <math.h>

// Problem constants
#define BATCH 8
#define CIN   256
#define COUT  256
#define HH    64
#define WW    64
#define K2    9

// ---------------- scratch (__device__ globals; no allocation) ----------------
__device__ float g_xt[BATCH * HH * WW * CIN];        // NHWC x          (32 MB)
__device__ float g_wt[K2 * CIN * COUT];              // [k][c][o]       (2.25 MB)
__device__ float g_wcomb[K2 * CIN * 32];             // [k][c][32] 18 off + 9 mask + pad
__device__ float g_biasc[32];
__device__ float g_offmask[BATCH * HH * WW * 32];    // per-pixel: 18 off, 9 mask (4 MB)

// ---------------- kernel 1: NCHW -> NHWC transpose ----------------
__global__ void transpose_x_kernel(const float* __restrict__ x)
{
    __shared__ float tile[32][33];
    int bh = blockIdx.z;             // b*64 + h
    int b = bh >> 6, h = bh & 63;
    int wbase = blockIdx.x * 32;
    int cbase = blockIdx.y * 32;
    int tx = threadIdx.x, ty = threadIdx.y;

    int wi = wbase + tx;
#pragma unroll
    for (int j = 0; j < 4; j++) {
        int c = cbase + ty + j * 8;
        tile[ty + j * 8][tx] = x[((b * CIN + c) * HH + h) * WW + wi];
    }
    __syncthreads();
    int c2 = cbase + tx;
#pragma unroll
    for (int j = 0; j < 4; j++) {
        int w2 = wbase + ty + j * 8;
        g_xt[((bh) * WW + w2) * CIN + c2] = tile[tx][ty + j * 8];
    }
}

// ---------------- kernel 2: pack main weight [o][c][k] -> [k][c][o] ----------------
__global__ void pack_wt_kernel(const float* __restrict__ weight)
{
    int i = blockIdx.x * blockDim.x + threadIdx.x;
    if (i >= K2 * CIN * COUT) return;
    int o = i & 255;
    int c = (i >> 8) & 255;
    int k = i >> 16;
    g_wt[i] = weight[(o * CIN + c) * K2 + k];
}

// ---------------- kernel 3: pack offset+mask weights -> [k][c][32], and bias ----------------
__global__ void pack_wcomb_kernel(const float* __restrict__ offset_w,
                                  const float* __restrict__ offset_b,
                                  const float* __restrict__ mod_w,
                                  const float* __restrict__ mod_b)
{
    int i = blockIdx.x * blockDim.x + threadIdx.x;
    if (i < K2 * CIN * 32) {
        int o = i & 31;
        int c = (i >> 5) & 255;
        int k = i >> 13;
        float v = 0.f;
        if (o < 18)      v = offset_w[(o * CIN + c) * K2 + k];
        else if (o < 27) v = mod_w[((o - 18) * CIN + c) * K2 + k];
        g_wcomb[i] = v;
    }
    if (i < 32) {
        float bv = 0.f;
        if (i < 18) bv = offset_b[i];
        else if (i < 27) bv = mod_b[i - 18];
        g_biasc[i] = bv;
    }
}

// ---------------- kernel 4: offset/mask 3x3 conv (C=256 -> 27) ----------------
// block = one (b,h) row of 64 pixels; 256 threads: o = t&31 (27 used), pg = t>>5 (8 px each)
#define OM_CC 16
__global__ __launch_bounds__(256) void offmask_kernel()
{
    __shared__ float xs[3 * OM_CC * 67];     // [row][cc][col 0..65 (pad 67)]
    __shared__ float ws[K2 * OM_CC * 32];    // [k][cc][o]

    int bid = blockIdx.x;
    int b = bid >> 6, h = bid & 63;
    int t = threadIdx.x;
    int o = t & 31;
    int pg = t >> 5;

    float acc[8];
#pragma unroll
    for (int i = 0; i < 8; i++) acc[i] = 0.f;

    for (int c0 = 0; c0 < CIN; c0 += OM_CC) {
        // stage x patch: rows h-1..h+1, cols -1..64, channels c0..c0+15
        for (int e = t; e < 3 * 66 * 4; e += 256) {
            int c4 = e & 3;
            int tmp = e >> 2;
            int col = tmp % 66;
            int r = tmp / 66;
            int y = h - 1 + r;
            int x = col - 1;
            float4 v = make_float4(0.f, 0.f, 0.f, 0.f);
            if ((unsigned)y < 64u && (unsigned)x < 64u)
                v = *(const float4*)&g_xt[(((b * HH + y) * WW + x) * CIN) + c0 + c4 * 4];
            int cb = c4 * 4;
            xs[(r * OM_CC + cb + 0) * 67 + col] = v.x;
            xs[(r * OM_CC + cb + 1) * 67 + col] = v.y;
            xs[(r * OM_CC + cb + 2) * 67 + col] = v.z;
            xs[(r * OM_CC + cb + 3) * 67 + col] = v.w;
        }
        // stage weights chunk
        for (int e = t; e < K2 * OM_CC * 32 / 4; e += 256) {
            int k = e / (OM_CC * 8);
            int rem = e % (OM_CC * 8);
            ((float4*)ws)[e] = ((const float4*)g_wcomb)[(k * CIN + c0) * 8 + rem];
        }
        __syncthreads();

        for (int cc = 0; cc < OM_CC; cc++) {
#pragma unroll
            for (int k = 0; k < K2; k++) {
                float wv = ws[(k * OM_CC + cc) * 32 + o];
                int r = k / 3, dj = k % 3;
                const float* xp = &xs[(r * OM_CC + cc) * 67 + pg * 8 + dj];
#pragma unroll
                for (int i = 0; i < 8; i++) acc[i] += wv * xp[i];
            }
        }
        __syncthreads();
    }

    if (o < 27) {
        float bv = g_biasc[o];
#pragma unroll
        for (int i = 0; i < 8; i++) {
            float v = acc[i] + bv;
            if (o >= 18) v = 2.f / (1.f + expf(-v));   // mask = 2*sigmoid
            g_offmask[((bid) * WW + pg * 8 + i) * 32 + o] = v;
        }
    }
}

// ---------------- kernel 5: deformable conv main contraction ----------------
// block = one (b,h) row (64 px), 256 threads: og = t&63 (4 outputs each), pg = t>>6 (16 px each)
__global__ __launch_bounds__(256, 2) void deform_kernel(const float* __restrict__ bias,
                                                        float* __restrict__ out)
{
    __shared__ int4   midx[WW * K2];   // 4 corner base indices into g_xt (element units)
    __shared__ float4 mwgt[WW * K2];   // 4 corner weights (mask & validity folded in)
    __shared__ float  ss[WW * 64];     // sampled [p][cc] for current (k, c-chunk)

    int bid = blockIdx.x;
    int b = bid >> 6, h = bid & 63;
    int t = threadIdx.x;
    int og = t & 63;
    int pg = t >> 6;

    // ---- per-block sampling metadata (p, k) ----
    for (int e = t; e < WW * K2; e += 256) {
        int p = e / K2;
        int k = e % K2;
        const float* om = &g_offmask[(bid * WW + p) * 32];
        float dy = om[2 * k];
        float dx = om[2 * k + 1];
        float m  = om[18 + k];
        int ki = k / 3, kj = k % 3;
        float py = dy + (float)(h - 1 + ki);
        float px = dx + (float)(p - 1 + kj);
        float y0f = floorf(py), x0f = floorf(px);
        float ly = py - y0f, lx = px - x0f;
        int y0 = (int)y0f, x0 = (int)x0f;
        int y1 = y0 + 1, x1 = x0 + 1;
        float wy0 = 1.f - ly, wx0 = 1.f - lx;
        bool vy0 = (y0 >= 0) && (y0 < HH);
        bool vy1 = (y1 >= 0) && (y1 < HH);
        bool vx0 = (x0 >= 0) && (x0 < WW);
        bool vx1 = (x1 >= 0) && (x1 < WW);
        float w00 = (vy0 && vx0) ? wy0 * wx0 * m : 0.f;
        float w01 = (vy0 && vx1) ? wy0 * lx  * m : 0.f;
        float w10 = (vy1 && vx0) ? ly  * wx0 * m : 0.f;
        float w11 = (vy1 && vx1) ? ly  * lx  * m : 0.f;
        int y0c = min(max(y0, 0), HH - 1);
        int y1c = min(max(y1, 0), HH - 1);
        int x0c = min(max(x0, 0), WW - 1);
        int x1c = min(max(x1, 0), WW - 1);
        midx[e] = make_int4(((b * HH + y0c) * WW + x0c) * CIN,
                            ((b * HH + y0c) * WW + x1c) * CIN,
                            ((b * HH + y1c) * WW + x0c) * CIN,
                            ((b * HH + y1c) * WW + x1c) * CIN);
        mwgt[e] = make_float4(w00, w01, w10, w11);
    }
    __syncthreads();

    float acc[64];
#pragma unroll
    for (int i = 0; i < 64; i++) acc[i] = 0.f;

    for (int k = 0; k < K2; k++) {
        for (int c0 = 0; c0 < CIN; c0 += 64) {
            // ---- stage sampled values: ss[p][cc], cc = 0..63 of chunk ----
#pragma unroll
            for (int g = t; g < WW * 16; g += 256) {
                int p = g >> 4;
                int c4 = g & 15;
                int e = p * K2 + k;
                int4 id = midx[e];
                float4 wg = mwgt[e];
                int cb = c0 + c4 * 4;
                float4 v0 = *(const float4*)&g_xt[id.x + cb];
                float4 v1 = *(const float4*)&g_xt[id.y + cb];
                float4 v2 = *(const float4*)&g_xt[id.z + cb];
                float4 v3 = *(const float4*)&g_xt[id.w + cb];
                float4 r;
                r.x = wg.x * v0.x + wg.y * v1.x + wg.z * v2.x + wg.w * v3.x;
                r.y = wg.x * v0.y + wg.y * v1.y + wg.z * v2.y + wg.w * v3.y;
                r.z = wg.x * v0.z + wg.y * v1.z + wg.z * v2.z + wg.w * v3.z;
                r.w = wg.x * v0.w + wg.y * v1.w + wg.z * v2.w + wg.w * v3.w;
                *(float4*)&ss[p * 64 + c4 * 4] = r;
            }
            __syncthreads();

            // ---- FMA phase: 4 outputs x 16 pixels per thread ----
            const float4* wp = (const float4*)&g_wt[(k * CIN + c0) * COUT] + og;
            const float*  sp = &ss[(pg * 16) * 64];
#pragma unroll 4
            for (int cc = 0; cc < 64; cc++) {
                float4 w4 = wp[cc * 64];
#pragma unroll
                for (int i = 0; i < 16; i++) {
                    float sv = sp[i * 64 + cc];
                    acc[i]      += w4.x * sv;
                    acc[16 + i] += w4.y * sv;
                    acc[32 + i] += w4.z * sv;
                    acc[48 + i] += w4.w * sv;
                }
            }
            __syncthreads();
        }
    }

    // ---- epilogue: bias + store (NCHW) ----
#pragma unroll
    for (int j = 0; j < 4; j++) {
        int o = og * 4 + j;
        float bv = bias[o];
        float* op = &out[((b * COUT + o) * HH + h) * WW + pg * 16];
#pragma unroll
        for (int i = 0; i < 16; i++) op[i] = acc[j * 16 + i] + bv;
    }
}

// ---------------- launcher ----------------
extern "C" void kernel_launch(void* const* d_in, const int* in_sizes, int n_in,
                              void* d_out, int out_size)
{
    const float* x        = (const float*)d_in[0];
    const float* offset_w = (const float*)d_in[1];
    const float* offset_b = (const float*)d_in[2];
    const float* mod_w    = (const float*)d_in[3];
    const float* mod_b    = (const float*)d_in[4];
    const float* weight   = (const float*)d_in[5];
    const float* bias     = (const float*)d_in[6];
    float* out = (float*)d_out;

    transpose_x_kernel<<<dim3(2, 8, BATCH * HH), dim3(32, 8)>>>(x);
    pack_wt_kernel<<<(K2 * CIN * COUT + 255) / 256, 256>>>(weight);
    pack_wcomb_kernel<<<(K2 * CIN * 32 + 255) / 256, 256>>>(offset_w, offset_b, mod_w, mod_b);
    offmask_kernel<<<BATCH * HH, 256>>>();
    deform_kernel<<<BATCH * HH, 256>>>(bias, out);
}

// round 2
// speedup vs baseline: 1.0001x; 1.0001x over previous
#include <cuda_runtime.h>
#include <math.h>

// Problem constants
#define BATCH 8
#define CIN   256
#define COUT  256
#define HH    64
#define WW    64
#define K2    9

// ---------------- scratch (__device__ globals; no allocation) ----------------
__device__ float g_xt[BATCH * HH * WW * CIN];        // NHWC x          (32 MB)
__device__ float g_wt[K2 * CIN * COUT];              // [k][c][o]       (2.25 MB)
__device__ float g_wcomb[K2 * CIN * 32];             // [k][c][32] 18 off + 9 mask + pad
__device__ float g_biasc[32];
__device__ float g_offmask[BATCH * HH * WW * 32];    // per-pixel: 18 off, 9 mask (4 MB)

// ---------------- kernel 1: NCHW -> NHWC transpose ----------------
__global__ void transpose_x_kernel(const float* __restrict__ x)
{
    __shared__ float tile[32][33];
    int bh = blockIdx.z;             // b*64 + h
    int b = bh >> 6, h = bh & 63;
    int wbase = blockIdx.x * 32;
    int cbase = blockIdx.y * 32;
    int tx = threadIdx.x, ty = threadIdx.y;

    int wi = wbase + tx;
#pragma unroll
    for (int j = 0; j < 4; j++) {
        int c = cbase + ty + j * 8;
        tile[ty + j * 8][tx] = x[((b * CIN + c) * HH + h) * WW + wi];
    }
    __syncthreads();
    int c2 = cbase + tx;
#pragma unroll
    for (int j = 0; j < 4; j++) {
        int w2 = wbase + ty + j * 8;
        g_xt[((bh) * WW + w2) * CIN + c2] = tile[tx][ty + j * 8];
    }
}

// ---------------- kernel 2: pack main weight [o][c][k] -> [k][c][o] ----------------
__global__ void pack_wt_kernel(const float* __restrict__ weight)
{
    int i = blockIdx.x * blockDim.x + threadIdx.x;
    if (i >= K2 * CIN * COUT) return;
    int o = i & 255;
    int c = (i >> 8) & 255;
    int k = i >> 16;
    g_wt[i] = weight[(o * CIN + c) * K2 + k];
}

// ---------------- kernel 3: pack offset+mask weights -> [k][c][32], and bias ----------------
__global__ void pack_wcomb_kernel(const float* __restrict__ offset_w,
                                  const float* __restrict__ offset_b,
                                  const float* __restrict__ mod_w,
                                  const float* __restrict__ mod_b)
{
    int i = blockIdx.x * blockDim.x + threadIdx.x;
    if (i < K2 * CIN * 32) {
        int o = i & 31;
        int c = (i >> 5) & 255;
        int k = i >> 13;
        float v = 0.f;
        if (o < 18)      v = offset_w[(o * CIN + c) * K2 + k];
        else if (o < 27) v = mod_w[((o - 18) * CIN + c) * K2 + k];
        g_wcomb[i] = v;
    }
    if (i < 32) {
        float bv = 0.f;
        if (i < 18) bv = offset_b[i];
        else if (i < 27) bv = mod_b[i - 18];
        g_biasc[i] = bv;
    }
}

// ---------------- kernel 4: offset/mask 3x3 conv (C=256 -> 27) ----------------
// block = one (b,h) row of 64 pixels; 256 threads: o = t&31 (27 used), pg = t>>5 (8 px each)
#define OM_CC 16
__global__ __launch_bounds__(256) void offmask_kernel()
{
    __shared__ float xs[3 * OM_CC * 67];     // [row][cc][col 0..65 (pad 67)]
    __shared__ float ws[K2 * OM_CC * 32];    // [k][cc][o]

    int bid = blockIdx.x;
    int b = bid >> 6, h = bid & 63;
    int t = threadIdx.x;
    int o = t & 31;
    int pg = t >> 5;

    float acc[8];
#pragma unroll
    for (int i = 0; i < 8; i++) acc[i] = 0.f;

    for (int c0 = 0; c0 < CIN; c0 += OM_CC) {
        // stage x patch: rows h-1..h+1, cols -1..64, channels c0..c0+15
        for (int e = t; e < 3 * 66 * 4; e += 256) {
            int c4 = e & 3;
            int tmp = e >> 2;
            int col = tmp % 66;
            int r = tmp / 66;
            int y = h - 1 + r;
            int x = col - 1;
            float4 v = make_float4(0.f, 0.f, 0.f, 0.f);
            if ((unsigned)y < 64u && (unsigned)x < 64u)
                v = *(const float4*)&g_xt[(((b * HH + y) * WW + x) * CIN) + c0 + c4 * 4];
            int cb = c4 * 4;
            xs[(r * OM_CC + cb + 0) * 67 + col] = v.x;
            xs[(r * OM_CC + cb + 1) * 67 + col] = v.y;
            xs[(r * OM_CC + cb + 2) * 67 + col] = v.z;
            xs[(r * OM_CC + cb + 3) * 67 + col] = v.w;
        }
        // stage weights chunk
        for (int e = t; e < K2 * OM_CC * 32 / 4; e += 256) {
            int k = e / (OM_CC * 8);
            int rem = e % (OM_CC * 8);
            ((float4*)ws)[e] = ((const float4*)g_wcomb)[(k * CIN + c0) * 8 + rem];
        }
        __syncthreads();

        for (int cc = 0; cc < OM_CC; cc++) {
#pragma unroll
            for (int k = 0; k < K2; k++) {
                float wv = ws[(k * OM_CC + cc) * 32 + o];
                int r = k / 3, dj = k % 3;
                const float* xp = &xs[(r * OM_CC + cc) * 67 + pg * 8 + dj];
#pragma unroll
                for (int i = 0; i < 8; i++) acc[i] += wv * xp[i];
            }
        }
        __syncthreads();
    }

    if (o < 27) {
        float bv = g_biasc[o];
#pragma unroll
        for (int i = 0; i < 8; i++) {
            float v = acc[i] + bv;
            if (o >= 18) v = 2.f / (1.f + expf(-v));   // mask = 2*sigmoid
            g_offmask[((bid) * WW + pg * 8 + i) * 32 + o] = v;
        }
    }
}

// ---------------- kernel 5: deformable conv main contraction ----------------
// block = one (b,h) row (64 px), 256 threads: og = t&63 (4 outputs each), pg = t>>6 (16 px each)
__global__ __launch_bounds__(256, 2) void deform_kernel(const float* __restrict__ bias,
                                                        float* __restrict__ out)
{
    __shared__ int4   midx[WW * K2];   // 4 corner base indices into g_xt (element units)
    __shared__ float4 mwgt[WW * K2];   // 4 corner weights (mask & validity folded in)
    __shared__ float  ss[WW * 64];     // sampled [p][cc] for current (k, c-chunk)

    int bid = blockIdx.x;
    int b = bid >> 6, h = bid & 63;
    int t = threadIdx.x;
    int og = t & 63;
    int pg = t >> 6;

    // ---- per-block sampling metadata (p, k) ----
    for (int e = t; e < WW * K2; e += 256) {
        int p = e / K2;
        int k = e % K2;
        const float* om = &g_offmask[(bid * WW + p) * 32];
        float dy = om[2 * k];
        float dx = om[2 * k + 1];
        float m  = om[18 + k];
        int ki = k / 3, kj = k % 3;
        float py = dy + (float)(h - 1 + ki);
        float px = dx + (float)(p - 1 + kj);
        float y0f = floorf(py), x0f = floorf(px);
        float ly = py - y0f, lx = px - x0f;
        int y0 = (int)y0f, x0 = (int)x0f;
        int y1 = y0 + 1, x1 = x0 + 1;
        float wy0 = 1.f - ly, wx0 = 1.f - lx;
        bool vy0 = (y0 >= 0) && (y0 < HH);
        bool vy1 = (y1 >= 0) && (y1 < HH);
        bool vx0 = (x0 >= 0) && (x0 < WW);
        bool vx1 = (x1 >= 0) && (x1 < WW);
        float w00 = (vy0 && vx0) ? wy0 * wx0 * m : 0.f;
        float w01 = (vy0 && vx1) ? wy0 * lx  * m : 0.f;
        float w10 = (vy1 && vx0) ? ly  * wx0 * m : 0.f;
        float w11 = (vy1 && vx1) ? ly  * lx  * m : 0.f;
        int y0c = min(max(y0, 0), HH - 1);
        int y1c = min(max(y1, 0), HH - 1);
        int x0c = min(max(x0, 0), WW - 1);
        int x1c = min(max(x1, 0), WW - 1);
        midx[e] = make_int4(((b * HH + y0c) * WW + x0c) * CIN,
                            ((b * HH + y0c) * WW + x1c) * CIN,
                            ((b * HH + y1c) * WW + x0c) * CIN,
                            ((b * HH + y1c) * WW + x1c) * CIN);
        mwgt[e] = make_float4(w00, w01, w10, w11);
    }
    __syncthreads();

    float acc[64];
#pragma unroll
    for (int i = 0; i < 64; i++) acc[i] = 0.f;

    for (int k = 0; k < K2; k++) {
        for (int c0 = 0; c0 < CIN; c0 += 64) {
            // ---- stage sampled values: ss[p][cc], cc = 0..63 of chunk ----
#pragma unroll
            for (int g = t; g < WW * 16; g += 256) {
                int p = g >> 4;
                int c4 = g & 15;
                int e = p * K2 + k;
                int4 id = midx[e];
                float4 wg = mwgt[e];
                int cb = c0 + c4 * 4;
                float4 v0 = *(const float4*)&g_xt[id.x + cb];
                float4 v1 = *(const float4*)&g_xt[id.y + cb];
                float4 v2 = *(const float4*)&g_xt[id.z + cb];
                float4 v3 = *(const float4*)&g_xt[id.w + cb];
                float4 r;
                r.x = wg.x * v0.x + wg.y * v1.x + wg.z * v2.x + wg.w * v3.x;
                r.y = wg.x * v0.y + wg.y * v1.y + wg.z * v2.y + wg.w * v3.y;
                r.z = wg.x * v0.z + wg.y * v1.z + wg.z * v2.z + wg.w * v3.z;
                r.w = wg.x * v0.w + wg.y * v1.w + wg.z * v2.w + wg.w * v3.w;
                *(float4*)&ss[p * 64 + c4 * 4] = r;
            }
            __syncthreads();

            // ---- FMA phase: 4 outputs x 16 pixels per thread ----
            const float4* wp = (const float4*)&g_wt[(k * CIN + c0) * COUT] + og;
            const float*  sp = &ss[(pg * 16) * 64];
#pragma unroll 4
            for (int cc = 0; cc < 64; cc++) {
                float4 w4 = wp[cc * 64];
#pragma unroll
                for (int i = 0; i < 16; i++) {
                    float sv = sp[i * 64 + cc];
                    acc[i]      += w4.x * sv;
                    acc[16 + i] += w4.y * sv;
                    acc[32 + i] += w4.z * sv;
                    acc[48 + i] += w4.w * sv;
                }
            }
            __syncthreads();
        }
    }

    // ---- epilogue: bias + store (NCHW) ----
#pragma unroll
    for (int j = 0; j < 4; j++) {
        int o = og * 4 + j;
        float bv = bias[o];
        float* op = &out[((b * COUT + o) * HH + h) * WW + pg * 16];
#pragma unroll
        for (int i = 0; i < 16; i++) op[i] = acc[j * 16 + i] + bv;
    }
}

// ---------------- launcher ----------------
extern "C" void kernel_launch(void* const* d_in, const int* in_sizes, int n_in,
                              void* d_out, int out_size)
{
    const float* x        = (const float*)d_in[0];
    const float* offset_w = (const float*)d_in[1];
    const float* offset_b = (const float*)d_in[2];
    const float* mod_w    = (const float*)d_in[3];
    const float* mod_b    = (const float*)d_in[4];
    const float* weight   = (const float*)d_in[5];
    const float* bias     = (const float*)d_in[6];
    float* out = (float*)d_out;

    transpose_x_kernel<<<dim3(2, 8, BATCH * HH), dim3(32, 8)>>>(x);
    pack_wt_kernel<<<(K2 * CIN * COUT + 255) / 256, 256>>>(weight);
    pack_wcomb_kernel<<<(K2 * CIN * 32 + 255) / 256, 256>>>(offset_w, offset_b, mod_w, mod_b);
    offmask_kernel<<<BATCH * HH, 256>>>();
    deform_kernel<<<BATCH * HH, 256>>>(bias, out);
}

// round 4
// speedup vs baseline: 2.3975x; 2.3974x over previous
#include <cuda_runtime.h>
#include <cstdint>
#include <math.h>

// Problem constants
#define BATCH 8
#define CIN   256
#define COUT  256
#define HH    64
#define WW    64
#define K2    9
#define NCHUNK 72          // 9 taps * 8 c-chunks of 32

// ---------------- scratch (__device__ globals; no allocation) ----------------
__device__ float g_xt[BATCH * HH * WW * CIN];        // NHWC x (32 MB)
__device__ float g_wtB[NCHUNK * 8192];               // fragment-ordered tf32 B tiles (2.25 MB)
__device__ float g_wcomb[K2 * CIN * 32];             // offset+mask weights [k][c][32]
__device__ float g_biasc[32];
__device__ float g_offmask[BATCH * HH * WW * 32];    // 18 off, 9 mask per pixel

// ---------------- helpers ----------------
__device__ __forceinline__ uint32_t smem_u32(const void* p) {
    uint32_t a;
    asm("{ .reg .u64 t; cvta.to.shared.u64 t, %1; cvt.u32.u64 %0, t; }" : "=r"(a) : "l"(p));
    return a;
}
__device__ __forceinline__ uint32_t f2tf32(float v) {
    uint32_t r;
    asm("cvt.rna.tf32.f32 %0, %1;" : "=r"(r) : "f"(v));
    return r;
}
__device__ __forceinline__ void cp_async16(uint32_t s, const void* g) {
    asm volatile("cp.async.cg.shared.global [%0], [%1], 16;" :: "r"(s), "l"(g) : "memory");
}
__device__ __forceinline__ void cp_commit() { asm volatile("cp.async.commit_group;" ::: "memory"); }
__device__ __forceinline__ void cp_wait0()  { asm volatile("cp.async.wait_group 0;" ::: "memory"); }

__device__ __forceinline__ void mma_tf32(float4& d, const uint4& a, const uint2& b) {
    asm volatile(
        "mma.sync.aligned.m16n8k8.row.col.f32.tf32.tf32.f32 "
        "{%0,%1,%2,%3}, {%4,%5,%6,%7}, {%8,%9}, {%0,%1,%2,%3};"
        : "+f"(d.x), "+f"(d.y), "+f"(d.z), "+f"(d.w)
        : "r"(a.x), "r"(a.y), "r"(a.z), "r"(a.w), "r"(b.x), "r"(b.y));
}

// ---------------- kernel 1: NCHW -> NHWC transpose ----------------
__global__ void transpose_x_kernel(const float* __restrict__ x)
{
    __shared__ float tile[32][33];
    int bh = blockIdx.z;
    int b = bh >> 6, h = bh & 63;
    int wbase = blockIdx.x * 32;
    int cbase = blockIdx.y * 32;
    int tx = threadIdx.x, ty = threadIdx.y;

    int wi = wbase + tx;
#pragma unroll
    for (int j = 0; j < 4; j++) {
        int c = cbase + ty + j * 8;
        tile[ty + j * 8][tx] = x[((b * CIN + c) * HH + h) * WW + wi];
    }
    __syncthreads();
    int c2 = cbase + tx;
#pragma unroll
    for (int j = 0; j < 4; j++) {
        int w2 = wbase + ty + j * 8;
        g_xt[((bh) * WW + w2) * CIN + c2] = tile[tx][ty + j * 8];
    }
}

// ---------------- kernel 2: pack main weight into fragment-ordered tf32 B tiles ----------------
// chunk q = tap*8 + cb. Within chunk: float index = ((n_blk*4 + ks)*32 + lane)*2 + r
//   n = n_blk*8 + (lane>>2), k = (lane&3) + r*4, c = cb*32 + ks*8 + k
__global__ void pack_wtB_kernel(const float* __restrict__ weight)
{
    int i = blockIdx.x * blockDim.x + threadIdx.x;
    if (i >= NCHUNK * 8192) return;
    int q = i >> 13;
    int rem = i & 8191;
    int r = rem & 1;
    int lane = (rem >> 1) & 31;
    int ks = (rem >> 6) & 3;
    int n_blk = rem >> 8;
    int tap = q >> 3;
    int n = n_blk * 8 + (lane >> 2);
    int k = (lane & 3) + r * 4;
    int c = (q & 7) * 32 + ks * 8 + k;
    float v = weight[(n * CIN + c) * K2 + tap];
    ((uint32_t*)g_wtB)[i] = f2tf32(v);
}

// ---------------- kernel 3: pack offset+mask weights ----------------
__global__ void pack_wcomb_kernel(const float* __restrict__ offset_w,
                                  const float* __restrict__ offset_b,
                                  const float* __restrict__ mod_w,
                                  const float* __restrict__ mod_b)
{
    int i = blockIdx.x * blockDim.x + threadIdx.x;
    if (i < K2 * CIN * 32) {
        int o = i & 31;
        int c = (i >> 5) & 255;
        int k = i >> 13;
        float v = 0.f;
        if (o < 18)      v = offset_w[(o * CIN + c) * K2 + k];
        else if (o < 27) v = mod_w[((o - 18) * CIN + c) * K2 + k];
        g_wcomb[i] = v;
    }
    if (i < 32) {
        float bv = 0.f;
        if (i < 18) bv = offset_b[i];
        else if (i < 27) bv = mod_b[i - 18];
        g_biasc[i] = bv;
    }
}

// ---------------- kernel 4: offset/mask 3x3 conv (C=256 -> 27) ----------------
#define OM_CC 16
__global__ __launch_bounds__(256) void offmask_kernel()
{
    __shared__ float xs[3 * OM_CC * 67];
    __shared__ float ws[K2 * OM_CC * 32];

    int bid = blockIdx.x;
    int b = bid >> 6, h = bid & 63;
    int t = threadIdx.x;
    int o = t & 31;
    int pg = t >> 5;

    float acc[8];
#pragma unroll
    for (int i = 0; i < 8; i++) acc[i] = 0.f;

    for (int c0 = 0; c0 < CIN; c0 += OM_CC) {
        for (int e = t; e < 3 * 66 * 4; e += 256) {
            int c4 = e & 3;
            int tmp = e >> 2;
            int col = tmp % 66;
            int r = tmp / 66;
            int y = h - 1 + r;
            int x = col - 1;
            float4 v = make_float4(0.f, 0.f, 0.f, 0.f);
            if ((unsigned)y < 64u && (unsigned)x < 64u)
                v = *(const float4*)&g_xt[(((b * HH + y) * WW + x) * CIN) + c0 + c4 * 4];
            int cb = c4 * 4;
            xs[(r * OM_CC + cb + 0) * 67 + col] = v.x;
            xs[(r * OM_CC + cb + 1) * 67 + col] = v.y;
            xs[(r * OM_CC + cb + 2) * 67 + col] = v.z;
            xs[(r * OM_CC + cb + 3) * 67 + col] = v.w;
        }
        for (int e = t; e < K2 * OM_CC * 32 / 4; e += 256) {
            int k = e / (OM_CC * 8);
            int rem = e % (OM_CC * 8);
            ((float4*)ws)[e] = ((const float4*)g_wcomb)[(k * CIN + c0) * 8 + rem];
        }
        __syncthreads();

        for (int cc = 0; cc < OM_CC; cc++) {
#pragma unroll
            for (int k = 0; k < K2; k++) {
                float wv = ws[(k * OM_CC + cc) * 32 + o];
                int r = k / 3, dj = k % 3;
                const float* xp = &xs[(r * OM_CC + cc) * 67 + pg * 8 + dj];
#pragma unroll
                for (int i = 0; i < 8; i++) acc[i] += wv * xp[i];
            }
        }
        __syncthreads();
    }

    if (o < 27) {
        float bv = g_biasc[o];
#pragma unroll
        for (int i = 0; i < 8; i++) {
            float v = acc[i] + bv;
            if (o >= 18) v = 2.f / (1.f + expf(-v));
            g_offmask[((bid) * WW + pg * 8 + i) * 32 + o] = v;
        }
    }
}

// ---------------- kernel 5: deformable conv via mma.sync tf32 ----------------
// Block = 2 rows: M=128 px, N=256, K=2304 in 72 chunks of 32. 512 threads = 16 warps (4M x 4N).
// A tile stored in fragment order: float idx = ((m_blk*4+ks)*32 + lane)*4 + j
//   j: 0=(r,c) 1=(r+8,c) 2=(r,c+4) 3=(r+8,c+4) with r=lane>>2 (within 16-row m_blk), c=lane&3 (within 8-k ks)
#define SM_MIDX   0
#define SM_MWGT   18432
#define SM_A0     36864
#define SM_A1     53248
#define SM_B0     69632
#define SM_B1     102400
#define SM_BIAS   135168
#define SM_TOTAL  136192

__global__ __launch_bounds__(512) void deform_mma_kernel(const float* __restrict__ bias,
                                                         float* __restrict__ out)
{
    extern __shared__ char smem[];
    uint32_t sb = smem_u32(smem);
    int t = threadIdx.x;
    int bid = blockIdx.x;
    int b = bid >> 5, h0 = (bid & 31) << 1;

    int4*   midx  = (int4*)(smem + SM_MIDX);
    float4* mwgt  = (float4*)(smem + SM_MWGT);
    float*  biasS = (float*)(smem + SM_BIAS);

    if (t < 256) biasS[t] = bias[t];

    // ---- per-block sampling metadata: 128 px x 9 taps ----
    for (int e = t; e < 128 * K2; e += 512) {
        int p = e / K2;
        int k = e - p * K2;
        int r = p >> 6, w = p & 63;
        int h = h0 + r;
        const float* om = &g_offmask[(((b * HH + h) * WW) + w) * 32];
        float dy = om[2 * k];
        float dx = om[2 * k + 1];
        float m  = om[18 + k];
        int ki = k / 3, kj = k - ki * 3;
        float py = dy + (float)(h - 1 + ki);
        float px = dx + (float)(w - 1 + kj);
        float y0f = floorf(py), x0f = floorf(px);
        float ly = py - y0f, lx = px - x0f;
        int y0 = (int)y0f, x0 = (int)x0f;
        int y1 = y0 + 1, x1 = x0 + 1;
        float wy0 = 1.f - ly, wx0 = 1.f - lx;
        bool vy0 = (y0 >= 0) && (y0 < HH);
        bool vy1 = (y1 >= 0) && (y1 < HH);
        bool vx0 = (x0 >= 0) && (x0 < WW);
        bool vx1 = (x1 >= 0) && (x1 < WW);
        float w00 = (vy0 && vx0) ? wy0 * wx0 * m : 0.f;
        float w01 = (vy0 && vx1) ? wy0 * lx  * m : 0.f;
        float w10 = (vy1 && vx0) ? ly  * wx0 * m : 0.f;
        float w11 = (vy1 && vx1) ? ly  * lx  * m : 0.f;
        int y0c = min(max(y0, 0), HH - 1);
        int y1c = min(max(y1, 0), HH - 1);
        int x0c = min(max(x0, 0), WW - 1);
        int x1c = min(max(x1, 0), WW - 1);
        midx[e] = make_int4(((b * HH + y0c) * WW + x0c) * CIN,
                            ((b * HH + y0c) * WW + x1c) * CIN,
                            ((b * HH + y1c) * WW + x0c) * CIN,
                            ((b * HH + y1c) * WW + x1c) * CIN);
        mwgt[e] = make_float4(w00, w01, w10, w11);
    }
    __syncthreads();

    // ---- staging identity: thread t samples pixel p, channels q4*8..q4*8+8 of each chunk ----
    int p_  = t >> 2;           // 0..127
    int q4  = t & 3;            // ks for this thread's channels
    int m_blk = p_ >> 4;
    int rr  = p_ & 15;
    int rA  = rr & 7;
    int r8  = rr >> 3;
    // A STS float-index base for (pass): ((m_blk*4 + q4)*32 + rA*4 + ci)*4 + (r8 + pass*2)
    int stsBase = ((m_blk * 4 + q4) * 32 + rA * 4) * 4 + r8;

    // ---- warp compute identity ----
    int wid = t >> 5, lane = t & 31;
    int wm = wid & 3, wn = wid >> 2;

    float4 acc[2][8];
#pragma unroll
    for (int mi = 0; mi < 2; mi++)
#pragma unroll
        for (int ni = 0; ni < 8; ni++) acc[mi][ni] = make_float4(0.f, 0.f, 0.f, 0.f);

    float* Abuf[2] = { (float*)(smem + SM_A0), (float*)(smem + SM_A1) };
    uint32_t AbufU[2] = { sb + SM_A0, sb + SM_A1 };
    uint32_t BbufU[2] = { sb + SM_B0, sb + SM_B1 };

    float4 g0, g1, g2, g3;      // prefetched corner values (4 channels)
    int4 id; float4 wg;

    // ---- prolog: fully stage chunk 0 ----
    {
        int tap = 0, c0 = 0;
        id = midx[p_ * K2 + tap];
        wg = mwgt[p_ * K2 + tap];
        // B chunk 0 via cp.async
        const char* bsrc = (const char*)(g_wtB) + 0;
#pragma unroll
        for (int i = 0; i < 4; i++)
            cp_async16(BbufU[0] + t * 16 + i * 8192, bsrc + t * 16 + i * 8192);
        cp_commit();
#pragma unroll
        for (int pass = 0; pass < 2; pass++) {
            int cb = c0 + q4 * 8 + pass * 4;
            g0 = *(const float4*)&g_xt[id.x + cb];
            g1 = *(const float4*)&g_xt[id.y + cb];
            g2 = *(const float4*)&g_xt[id.z + cb];
            g3 = *(const float4*)&g_xt[id.w + cb];
            float s0 = wg.x * g0.x + wg.y * g1.x + wg.z * g2.x + wg.w * g3.x;
            float s1 = wg.x * g0.y + wg.y * g1.y + wg.z * g2.y + wg.w * g3.y;
            float s2 = wg.x * g0.z + wg.y * g1.z + wg.z * g2.z + wg.w * g3.z;
            float s3 = wg.x * g0.w + wg.y * g1.w + wg.z * g2.w + wg.w * g3.w;
            uint32_t* A = (uint32_t*)Abuf[0];
            int base = stsBase + pass * 2;
            A[base + 0]  = f2tf32(s0);
            A[base + 4]  = f2tf32(s1);
            A[base + 8]  = f2tf32(s2);
            A[base + 12] = f2tf32(s3);
        }
        cp_wait0();
        __syncthreads();
    }

    // ---- main pipeline ----
    for (int q = 0; q < NCHUNK; q++) {
        int buf = q & 1, nbuf = buf ^ 1;
        bool pre = (q + 1 < NCHUNK);
        int tapn = (q + 1) >> 3;
        int c0n = ((q + 1) & 7) << 5;

        // issue prefetch loads for q+1 (pass 1)
        if (pre) {
            id = midx[p_ * K2 + tapn];
            wg = mwgt[p_ * K2 + tapn];
            int cb = c0n + q4 * 8;
            g0 = *(const float4*)&g_xt[id.x + cb];
            g1 = *(const float4*)&g_xt[id.y + cb];
            g2 = *(const float4*)&g_xt[id.z + cb];
            g3 = *(const float4*)&g_xt[id.w + cb];
            const char* bsrc = (const char*)(g_wtB) + (size_t)(q + 1) * 32768;
#pragma unroll
            for (int i = 0; i < 4; i++)
                cp_async16(BbufU[nbuf] + t * 16 + i * 8192, bsrc + t * 16 + i * 8192);
            cp_commit();
        }

        const float4* As = (const float4*)Abuf[buf];
        const float2* Bs = (const float2*)(smem + (buf ? SM_B1 : SM_B0));

        // compute ks = 0,1
#pragma unroll
        for (int ks = 0; ks < 2; ks++) {
            uint4 a[2];
            uint2 bfr[8];
#pragma unroll
            for (int mi = 0; mi < 2; mi++) {
                float4 af = As[((wm * 2 + mi) * 4 + ks) * 32 + lane];
                a[mi] = *(uint4*)&af;
            }
#pragma unroll
            for (int ni = 0; ni < 8; ni++) {
                float2 bf = Bs[((wn * 8 + ni) * 4 + ks) * 32 + lane];
                bfr[ni] = *(uint2*)&bf;
            }
#pragma unroll
            for (int mi = 0; mi < 2; mi++)
#pragma unroll
                for (int ni = 0; ni < 8; ni++)
                    mma_tf32(acc[mi][ni], a[mi], bfr[ni]);
        }

        // STS pass1 for q+1, then issue pass2 loads
        if (pre) {
            float s0 = wg.x * g0.x + wg.y * g1.x + wg.z * g2.x + wg.w * g3.x;
            float s1 = wg.x * g0.y + wg.y * g1.y + wg.z * g2.y + wg.w * g3.y;
            float s2 = wg.x * g0.z + wg.y * g1.z + wg.z * g2.z + wg.w * g3.z;
            float s3 = wg.x * g0.w + wg.y * g1.w + wg.z * g2.w + wg.w * g3.w;
            uint32_t* A = (uint32_t*)Abuf[nbuf];
            A[stsBase + 0]  = f2tf32(s0);
            A[stsBase + 4]  = f2tf32(s1);
            A[stsBase + 8]  = f2tf32(s2);
            A[stsBase + 12] = f2tf32(s3);
            int cb = c0n + q4 * 8 + 4;
            g0 = *(const float4*)&g_xt[id.x + cb];
            g1 = *(const float4*)&g_xt[id.y + cb];
            g2 = *(const float4*)&g_xt[id.z + cb];
            g3 = *(const float4*)&g_xt[id.w + cb];
        }

        // compute ks = 2,3
#pragma unroll
        for (int ks = 2; ks < 4; ks++) {
            uint4 a[2];
            uint2 bfr[8];
#pragma unroll
            for (int mi = 0; mi < 2; mi++) {
                float4 af = As[((wm * 2 + mi) * 4 + ks) * 32 + lane];
                a[mi] = *(uint4*)&af;
            }
#pragma unroll
            for (int ni = 0; ni < 8; ni++) {
                float2 bf = Bs[((wn * 8 + ni) * 4 + ks) * 32 + lane];
                bfr[ni] = *(uint2*)&bf;
            }
#pragma unroll
            for (int mi = 0; mi < 2; mi++)
#pragma unroll
                for (int ni = 0; ni < 8; ni++)
                    mma_tf32(acc[mi][ni], a[mi], bfr[ni]);
        }

        // STS pass2 for q+1
        if (pre) {
            float s0 = wg.x * g0.x + wg.y * g1.x + wg.z * g2.x + wg.w * g3.x;
            float s1 = wg.x * g0.y + wg.y * g1.y + wg.z * g2.y + wg.w * g3.y;
            float s2 = wg.x * g0.z + wg.y * g1.z + wg.z * g2.z + wg.w * g3.z;
            float s3 = wg.x * g0.w + wg.y * g1.w + wg.z * g2.w + wg.w * g3.w;
            uint32_t* A = (uint32_t*)Abuf[nbuf];
            A[stsBase + 2]  = f2tf32(s0);
            A[stsBase + 6]  = f2tf32(s1);
            A[stsBase + 10] = f2tf32(s2);
            A[stsBase + 14] = f2tf32(s3);
        }

        cp_wait0();
        __syncthreads();
    }

    // ---- epilogue: bias + scattered NCHW stores ----
    int gid = lane >> 2, tig = lane & 3;
#pragma unroll
    for (int mi = 0; mi < 2; mi++) {
        int p0 = wm * 32 + mi * 16 + gid;
        int p1 = p0 + 8;
        int h_0 = h0 + (p0 >> 6), w_0 = p0 & 63;
        int h_1 = h0 + (p1 >> 6), w_1 = p1 & 63;
#pragma unroll
        for (int ni = 0; ni < 8; ni++) {
            int o0 = wn * 64 + ni * 8 + tig * 2;
            int o1 = o0 + 1;
            float4 d = acc[mi][ni];
            out[((b * COUT + o0) * HH + h_0) * WW + w_0] = d.x + biasS[o0];
            out[((b * COUT + o1) * HH + h_0) * WW + w_0] = d.y + biasS[o1];
            out[((b * COUT + o0) * HH + h_1) * WW + w_1] = d.z + biasS[o0];
            out[((b * COUT + o1) * HH + h_1) * WW + w_1] = d.w + biasS[o1];
        }
    }
}

// ---------------- launcher ----------------
extern "C" void kernel_launch(void* const* d_in, const int* in_sizes, int n_in,
                              void* d_out, int out_size)
{
    const float* x        = (const float*)d_in[0];
    const float* offset_w = (const float*)d_in[1];
    const float* offset_b = (const float*)d_in[2];
    const float* mod_w    = (const float*)d_in[3];
    const float* mod_b    = (const float*)d_in[4];
    const float* weight   = (const float*)d_in[5];
    const float* bias     = (const float*)d_in[6];
    float* out = (float*)d_out;

    cudaFuncSetAttribute(deform_mma_kernel, cudaFuncAttributeMaxDynamicSharedMemorySize, SM_TOTAL);

    transpose_x_kernel<<<dim3(2, 8, BATCH * HH), dim3(32, 8)>>>(x);
    pack_wtB_kernel<<<(NCHUNK * 8192 + 255) / 256, 256>>>(weight);
    pack_wcomb_kernel<<<(K2 * CIN * 32 + 255) / 256, 256>>>(offset_w, offset_b, mod_w, mod_b);
    offmask_kernel<<<BATCH * HH, 256>>>();
    deform_mma_kernel<<<BATCH * HH / 2, 512, SM_TOTAL>>>(bias, out);
}

// round 8
// speedup vs baseline: 4.3132x; 1.7990x over previous
#include <cuda_runtime.h>
#include <cuda_fp16.h>
#include <cstdint>
#include <math.h>

// Problem constants
#define BATCH 8
#define CIN   256
#define COUT  256
#define HH    64
#define WW    64
#define K2    9
#define NCHUNK 72          // 9 taps * 8 c-chunks of 32

// ---------------- scratch (__device__ globals; no allocation) ----------------
__device__ float  g_xt[BATCH * HH * WW * CIN];       // NHWC x, fp32 (32 MB)
__device__ __half g_wtB[NCHUNK * 8192];              // fp16 fragment-ordered main B tiles (1.125 MB)
__device__ __half g_wtOM[NCHUNK * 1024];             // fp16 fragment-ordered offmask B tiles (147 KB)
__device__ float  g_offmask[BATCH * HH * WW * 32];   // 18 off, 9 mask per pixel (fp32)

// ---------------- helpers ----------------
__device__ __forceinline__ uint32_t smem_u32(const void* p) {
    uint32_t a;
    asm("{ .reg .u64 t; cvta.to.shared.u64 t, %1; cvt.u32.u64 %0, t; }" : "=r"(a) : "l"(p));
    return a;
}
__device__ __forceinline__ void cp_async16(uint32_t s, const void* g) {
    asm volatile("cp.async.cg.shared.global [%0], [%1], 16;" :: "r"(s), "l"(g) : "memory");
}
__device__ __forceinline__ void cp_commit() { asm volatile("cp.async.commit_group;" ::: "memory"); }
__device__ __forceinline__ void cp_wait0()  { asm volatile("cp.async.wait_group 0;" ::: "memory"); }

__device__ __forceinline__ void mma_f16(float4& d, const uint4& a, const uint2& b) {
    asm volatile(
        "mma.sync.aligned.m16n8k16.row.col.f32.f16.f16.f32 "
        "{%0,%1,%2,%3}, {%4,%5,%6,%7}, {%8,%9}, {%0,%1,%2,%3};"
        : "+f"(d.x), "+f"(d.y), "+f"(d.z), "+f"(d.w)
        : "r"(a.x), "r"(a.y), "r"(a.z), "r"(a.w), "r"(b.x), "r"(b.y));
}

// ---------------- kernel 1: NCHW -> NHWC transpose (fp32) ----------------
__global__ void transpose_x_kernel(const float* __restrict__ x)
{
    __shared__ float tile[32][33];
    int bh = blockIdx.z;
    int b = bh >> 6, h = bh & 63;
    int wbase = blockIdx.x * 32;
    int cbase = blockIdx.y * 32;
    int tx = threadIdx.x, ty = threadIdx.y;

    int wi = wbase + tx;
#pragma unroll
    for (int j = 0; j < 4; j++) {
        int c = cbase + ty + j * 8;
        tile[ty + j * 8][tx] = x[((b * CIN + c) * HH + h) * WW + wi];
    }
    __syncthreads();
    int c2 = cbase + tx;
#pragma unroll
    for (int j = 0; j < 4; j++) {
        int w2 = wbase + ty + j * 8;
        g_xt[((bh) * WW + w2) * CIN + c2] = tile[tx][ty + j * 8];
    }
}

// ---------------- kernel 2: pack main weight into fp16 fragment-ordered B tiles ----------------
// half2 word index i: q=i>>12, w=i&4095: r=w&1, lane=(w>>1)&31, ks=(w>>6)&1, n_blk=(w>>7)&31
__global__ void pack_wtB_kernel(const float* __restrict__ weight)
{
    int i = blockIdx.x * blockDim.x + threadIdx.x;
    if (i >= NCHUNK * 4096) return;
    int q = i >> 12;
    int w = i & 4095;
    int r = w & 1;
    int lane = (w >> 1) & 31;
    int ks = (w >> 6) & 1;
    int n_blk = (w >> 7) & 31;
    int tap = q >> 3;
    int n = n_blk * 8 + (lane >> 2);
    int c = (q & 7) * 32 + ks * 16 + (lane & 3) * 2 + r * 8;
    float v0 = weight[(n * CIN + c) * K2 + tap];
    float v1 = weight[(n * CIN + c + 1) * K2 + tap];
    ((__half2*)g_wtB)[i] = __floats2half2_rn(v0, v1);
}

// ---------------- kernel 2b: pack offset+mask weights into fp16 B tiles (N=32 padded) ----------------
__global__ void pack_wtOM_kernel(const float* __restrict__ offset_w,
                                 const float* __restrict__ mod_w)
{
    int i = blockIdx.x * blockDim.x + threadIdx.x;
    if (i >= NCHUNK * 512) return;
    int q = i >> 9;
    int w = i & 511;
    int r = w & 1;
    int lane = (w >> 1) & 31;
    int ks = (w >> 6) & 1;
    int n_blk = (w >> 7) & 3;
    int tap = q >> 3;
    int n = n_blk * 8 + (lane >> 2);
    int c = (q & 7) * 32 + ks * 16 + (lane & 3) * 2 + r * 8;
    float v0 = 0.f, v1 = 0.f;
    if (n < 18)      { v0 = offset_w[(n * CIN + c) * K2 + tap]; v1 = offset_w[(n * CIN + c + 1) * K2 + tap]; }
    else if (n < 27) { v0 = mod_w[((n - 18) * CIN + c) * K2 + tap]; v1 = mod_w[((n - 18) * CIN + c + 1) * K2 + tap]; }
    ((__half2*)g_wtOM)[i] = __floats2half2_rn(v0, v1);
}

// ---------------- kernel 3: offset/mask conv via fp16 mma (A from fp32 x) ----------------
// Block = 1 row (64 px): M=64, N=32, K=2304 in 72 chunks. 256 threads = 8 warps (4M x 2N).
__global__ __launch_bounds__(256) void offmask_mma_kernel(const float* __restrict__ offset_b,
                                                          const float* __restrict__ mod_b)
{
    __shared__ __align__(16) char smA[2][4096];   // A frag: [m_blk4][ks16 2][lane32][16B]
    __shared__ __align__(16) char smB[2][2048];   // B frag: [n_blk4][ks16 2][lane32][8B]

    int t = threadIdx.x;
    int wid = t >> 5, lane = t & 31;
    int bid = blockIdx.x;
    int b = bid >> 6, h = bid & 63;

    uint32_t sbB[2] = { smem_u32(smB[0]), smem_u32(smB[1]) };

    // staging identity: pixel p_=t>>2, channels q4*8..+7
    int p_ = t >> 2, q4 = t & 3;
    int m_blk = p_ >> 4, rr = p_ & 15, rA = rr & 7, r8 = rr >> 3;
    int jw = r8 + 2 * (q4 & 1);
    int ks16s = q4 >> 1;
    int stsBase = ((m_blk * 2 + ks16s) * 32 + 4 * rA) * 4 + jw;   // half2-word index

    int wm = wid & 3, wn = wid >> 2;

    float4 acc[2];
    acc[0] = make_float4(0.f, 0.f, 0.f, 0.f);
    acc[1] = make_float4(0.f, 0.f, 0.f, 0.f);

    float4 ga0, ga1;

    auto loadA = [&](int q) {
        int tap = q >> 3;
        int ki = tap / 3, kj = tap - ki * 3;
        int y = h + ki - 1;
        int xc = p_ + kj - 1;
        if ((unsigned)y < 64u && (unsigned)xc < 64u) {
            const float* src = &g_xt[(((b * HH + y) * WW + xc) * CIN) + (q & 7) * 32 + q4 * 8];
            ga0 = *(const float4*)src;
            ga1 = *(const float4*)(src + 4);
        } else {
            ga0 = make_float4(0.f, 0.f, 0.f, 0.f);
            ga1 = make_float4(0.f, 0.f, 0.f, 0.f);
        }
    };
    auto stsA = [&](int buf) {
        __half2* Aw = (__half2*)smA[buf];
        Aw[stsBase + 0 * 4] = __floats2half2_rn(ga0.x, ga0.y);
        Aw[stsBase + 1 * 4] = __floats2half2_rn(ga0.z, ga0.w);
        Aw[stsBase + 2 * 4] = __floats2half2_rn(ga1.x, ga1.y);
        Aw[stsBase + 3 * 4] = __floats2half2_rn(ga1.z, ga1.w);
    };

    // prologue: stage chunk 0
    loadA(0);
    stsA(0);
    if (t < 128) cp_async16(sbB[0] + t * 16, (const char*)g_wtOM + t * 16);
    cp_commit();
    cp_wait0();
    __syncthreads();

    for (int q = 0; q < NCHUNK; q++) {
        int buf = q & 1, nbuf = buf ^ 1;
        bool pre = (q + 1 < NCHUNK);
        if (pre) {
            loadA(q + 1);
            if (t < 128) cp_async16(sbB[nbuf] + t * 16, (const char*)g_wtOM + (size_t)(q + 1) * 2048 + t * 16);
            cp_commit();
        }

        const uint4* As = (const uint4*)smA[buf];
        const uint2* Bs = (const uint2*)smB[buf];
#pragma unroll
        for (int ks = 0; ks < 2; ks++) {
            uint4 a = As[(wm * 2 + ks) * 32 + lane];
#pragma unroll
            for (int ni = 0; ni < 2; ni++) {
                uint2 bf = Bs[((wn * 2 + ni) * 2 + ks) * 32 + lane];
                mma_f16(acc[ni], a, bf);
            }
        }

        if (pre) stsA(nbuf);
        cp_wait0();
        __syncthreads();
    }

    // epilogue: bias + sigmoid(mask), store fp32
    int r0 = lane >> 2;
#pragma unroll
    for (int ni = 0; ni < 2; ni++) {
        int nb = wn * 16 + ni * 8 + (lane & 3) * 2;
        const float* a4 = (const float*)&acc[ni];
#pragma unroll
        for (int rr2 = 0; rr2 < 2; rr2++) {
            int px = wm * 16 + r0 + rr2 * 8;
#pragma unroll
            for (int cc = 0; cc < 2; cc++) {
                int n = nb + cc;
                if (n >= 27) continue;
                float v = a4[rr2 * 2 + cc];
                if (n < 18) v += offset_b[n];
                else        v = 2.f / (1.f + expf(-(v + mod_b[n - 18])));
                g_offmask[(bid * WW + px) * 32 + n] = v;
            }
        }
    }
}

// ---------------- kernel 4: deformable conv via fp16 mma (A sampled from fp32 x) ----------------
// Block = 2 rows: M=128 px, N=256, K=2304 in 72 chunks of 32. 512 threads = 16 warps (4M x 4N).
// A tile per buffer: 128 rows x 32 k x 2B = 8192 B.  B tile per buffer: 256 n x 32 k x 2B = 16384 B.
#define SM_MIDX   0
#define SM_MWGT   18432
#define SM_A0     36864
#define SM_A1     45056
#define SM_B0     53248
#define SM_B1     69632
#define SM_BIAS   86016
#define SM_TOTAL  87040

__global__ __launch_bounds__(512) void deform_mma_kernel(const float* __restrict__ bias,
                                                         float* __restrict__ out)
{
    extern __shared__ char smem[];
    uint32_t sb = smem_u32(smem);
    int t = threadIdx.x;
    int bid = blockIdx.x;
    int b = bid >> 5, h0 = (bid & 31) << 1;

    int4*   midx  = (int4*)(smem + SM_MIDX);
    float4* mwgt  = (float4*)(smem + SM_MWGT);
    float*  biasS = (float*)(smem + SM_BIAS);

    if (t < 256) biasS[t] = bias[t];

    // ---- per-block sampling metadata: 128 px x 9 taps ----
    for (int e = t; e < 128 * K2; e += 512) {
        int p = e / K2;
        int k = e - p * K2;
        int r = p >> 6, w = p & 63;
        int h = h0 + r;
        const float* om = &g_offmask[(((b * HH + h) * WW) + w) * 32];
        float dy = om[2 * k];
        float dx = om[2 * k + 1];
        float m  = om[18 + k];
        int ki = k / 3, kj = k - ki * 3;
        float py = dy + (float)(h - 1 + ki);
        float px = dx + (float)(w - 1 + kj);
        float y0f = floorf(py), x0f = floorf(px);
        float ly = py - y0f, lx = px - x0f;
        int y0 = (int)y0f, x0 = (int)x0f;
        int y1 = y0 + 1, x1 = x0 + 1;
        float wy0 = 1.f - ly, wx0 = 1.f - lx;
        bool vy0 = (y0 >= 0) && (y0 < HH);
        bool vy1 = (y1 >= 0) && (y1 < HH);
        bool vx0 = (x0 >= 0) && (x0 < WW);
        bool vx1 = (x1 >= 0) && (x1 < WW);
        float w00 = (vy0 && vx0) ? wy0 * wx0 * m : 0.f;
        float w01 = (vy0 && vx1) ? wy0 * lx  * m : 0.f;
        float w10 = (vy1 && vx0) ? ly  * wx0 * m : 0.f;
        float w11 = (vy1 && vx1) ? ly  * lx  * m : 0.f;
        int y0c = min(max(y0, 0), HH - 1);
        int y1c = min(max(y1, 0), HH - 1);
        int x0c = min(max(x0, 0), WW - 1);
        int x1c = min(max(x1, 0), WW - 1);
        midx[e] = make_int4(((b * HH + y0c) * WW + x0c) * CIN,
                            ((b * HH + y0c) * WW + x1c) * CIN,
                            ((b * HH + y1c) * WW + x0c) * CIN,
                            ((b * HH + y1c) * WW + x1c) * CIN);
        mwgt[e] = make_float4(w00, w01, w10, w11);
    }
    __syncthreads();

    // staging identity: pixel p_=t>>2, channels q4*8..+7 of chunk
    int p_ = t >> 2, q4 = t & 3;
    int m_blk = p_ >> 4, rr = p_ & 15, rA = rr & 7, r8 = rr >> 3;
    int jw = r8 + 2 * (q4 & 1);
    int ks16s = q4 >> 1;
    int stsBase = ((m_blk * 2 + ks16s) * 32 + 4 * rA) * 4 + jw;   // half2-word index in A tile

    int wid = t >> 5, lane = t & 31;
    int wm = wid & 3, wn = wid >> 2;

    float4 acc[2][8];
#pragma unroll
    for (int mi = 0; mi < 2; mi++)
#pragma unroll
        for (int ni = 0; ni < 8; ni++) acc[mi][ni] = make_float4(0.f, 0.f, 0.f, 0.f);

    char* Abuf[2] = { smem + SM_A0, smem + SM_A1 };
    char* Bbuf[2] = { smem + SM_B0, smem + SM_B1 };
    uint32_t BbufU[2] = { sb + SM_B0, sb + SM_B1 };

    float4 g0, g1, g2, g3;      // one pass worth of corner values (4 channels, fp32)
    int4 id; float4 wg;

    // combine current pass into 2 half2 words at stsBase + pass*2*4
    auto stsPass = [&](int buf, int pass) {
        float sx = wg.x * g0.x + wg.y * g1.x + wg.z * g2.x + wg.w * g3.x;
        float sy = wg.x * g0.y + wg.y * g1.y + wg.z * g2.y + wg.w * g3.y;
        float sz = wg.x * g0.z + wg.y * g1.z + wg.z * g2.z + wg.w * g3.z;
        float sw = wg.x * g0.w + wg.y * g1.w + wg.z * g2.w + wg.w * g3.w;
        __half2* Aw = (__half2*)Abuf[buf];
        Aw[stsBase + (pass * 2 + 0) * 4] = __floats2half2_rn(sx, sy);
        Aw[stsBase + (pass * 2 + 1) * 4] = __floats2half2_rn(sz, sw);
    };
    auto loadPass = [&](int cb) {
        g0 = *(const float4*)&g_xt[id.x + cb];
        g1 = *(const float4*)&g_xt[id.y + cb];
        g2 = *(const float4*)&g_xt[id.z + cb];
        g3 = *(const float4*)&g_xt[id.w + cb];
    };

    // prologue: stage chunk 0
    {
        id = midx[p_ * K2 + 0];
        wg = mwgt[p_ * K2 + 0];
#pragma unroll
        for (int i = 0; i < 2; i++)
            cp_async16(BbufU[0] + t * 16 + i * 8192, (const char*)g_wtB + t * 16 + i * 8192);
        cp_commit();
        loadPass(q4 * 8);
        stsPass(0, 0);
        loadPass(q4 * 8 + 4);
        stsPass(0, 1);
        cp_wait0();
        __syncthreads();
    }

    for (int q = 0; q < NCHUNK; q++) {
        int buf = q & 1, nbuf = buf ^ 1;
        bool pre = (q + 1 < NCHUNK);

        if (pre) {
            int qq = q + 1;
            int tap = qq >> 3;
            id = midx[p_ * K2 + tap];
            wg = mwgt[p_ * K2 + tap];
            loadPass(((qq & 7) << 5) + q4 * 8);
            const char* bsrc = (const char*)g_wtB + (size_t)qq * 16384;
#pragma unroll
            for (int i = 0; i < 2; i++)
                cp_async16(BbufU[nbuf] + t * 16 + i * 8192, bsrc + t * 16 + i * 8192);
            cp_commit();
        }

        const uint4* As = (const uint4*)Abuf[buf];
        const uint2* Bs = (const uint2*)Bbuf[buf];

        // ks = 0
        {
            uint4 a0 = As[((wm * 2 + 0) * 2 + 0) * 32 + lane];
            uint4 a1 = As[((wm * 2 + 1) * 2 + 0) * 32 + lane];
#pragma unroll
            for (int ni = 0; ni < 8; ni++) {
                uint2 bf = Bs[((wn * 8 + ni) * 2 + 0) * 32 + lane];
                mma_f16(acc[0][ni], a0, bf);
                mma_f16(acc[1][ni], a1, bf);
            }
        }

        // STS pass0 for q+1, load pass1 (overlap with MMA)
        if (pre) {
            stsPass(nbuf, 0);
            loadPass((((q + 1) & 7) << 5) + q4 * 8 + 4);
        }

        // ks = 1
        {
            uint4 a0 = As[((wm * 2 + 0) * 2 + 1) * 32 + lane];
            uint4 a1 = As[((wm * 2 + 1) * 2 + 1) * 32 + lane];
#pragma unroll
            for (int ni = 0; ni < 8; ni++) {
                uint2 bf = Bs[((wn * 8 + ni) * 2 + 1) * 32 + lane];
                mma_f16(acc[0][ni], a0, bf);
                mma_f16(acc[1][ni], a1, bf);
            }
        }

        if (pre) stsPass(nbuf, 1);

        cp_wait0();
        __syncthreads();
    }

    // ---- epilogue: bias + scattered NCHW stores ----
    int gid = lane >> 2, tig = lane & 3;
#pragma unroll
    for (int mi = 0; mi < 2; mi++) {
        int p0 = wm * 32 + mi * 16 + gid;
        int p1 = p0 + 8;
        int h_0 = h0 + (p0 >> 6), w_0 = p0 & 63;
        int h_1 = h0 + (p1 >> 6), w_1 = p1 & 63;
#pragma unroll
        for (int ni = 0; ni < 8; ni++) {
            int o0 = wn * 64 + ni * 8 + tig * 2;
            int o1 = o0 + 1;
            float4 d = acc[mi][ni];
            out[((b * COUT + o0) * HH + h_0) * WW + w_0] = d.x + biasS[o0];
            out[((b * COUT + o1) * HH + h_0) * WW + w_0] = d.y + biasS[o1];
            out[((b * COUT + o0) * HH + h_1) * WW + w_1] = d.z + biasS[o0];
            out[((b * COUT + o1) * HH + h_1) * WW + w_1] = d.w + biasS[o1];
        }
    }
}

// ---------------- launcher ----------------
extern "C" void kernel_launch(void* const* d_in, const int* in_sizes, int n_in,
                              void* d_out, int out_size)
{
    const float* x        = (const float*)d_in[0];
    const float* offset_w = (const float*)d_in[1];
    const float* offset_b = (const float*)d_in[2];
    const float* mod_w    = (const float*)d_in[3];
    const float* mod_b    = (const float*)d_in[4];
    const float* weight   = (const float*)d_in[5];
    const float* bias     = (const float*)d_in[6];
    float* out = (float*)d_out;

    cudaFuncSetAttribute(deform_mma_kernel, cudaFuncAttributeMaxDynamicSharedMemorySize, SM_TOTAL);

    transpose_x_kernel<<<dim3(2, 8, BATCH * HH), dim3(32, 8)>>>(x);
    pack_wtB_kernel<<<(NCHUNK * 4096 + 255) / 256, 256>>>(weight);
    pack_wtOM_kernel<<<(NCHUNK * 512 + 255) / 256, 256>>>(offset_w, mod_w);
    offmask_mma_kernel<<<BATCH * HH, 256>>>(offset_b, mod_b);
    deform_mma_kernel<<<BATCH * HH / 2, 512, SM_TOTAL>>>(bias, out);
}

// round 9
// speedup vs baseline: 4.3371x; 1.0055x over previous
#include <cuda_runtime.h>
#include <cuda_fp16.h>
#include <cstdint>
#include <math.h>

// Problem constants
#define BATCH 8
#define CIN   256
#define COUT  256
#define HH    64
#define WW    64
#define K2    9
#define NCHUNK 72          // 9 taps * 8 c-chunks of 32

// ---------------- scratch (__device__ globals; no allocation) ----------------
__device__ float  g_xt[BATCH * HH * WW * CIN];       // NHWC x, fp32 (32 MB)
__device__ __half g_wtB[NCHUNK * 8192];              // fp16 fragment-ordered main B tiles (1.125 MB)
__device__ __half g_wtOM[NCHUNK * 1024];             // fp16 fragment-ordered offmask B tiles (147 KB)
__device__ float  g_offmask[BATCH * HH * WW * 32];   // 18 off, 9 mask per pixel (fp32)

// ---------------- helpers ----------------
__device__ __forceinline__ uint32_t smem_u32(const void* p) {
    uint32_t a;
    asm("{ .reg .u64 t; cvta.to.shared.u64 t, %1; cvt.u32.u64 %0, t; }" : "=r"(a) : "l"(p));
    return a;
}
__device__ __forceinline__ void cp_async16(uint32_t s, const void* g) {
    asm volatile("cp.async.cg.shared.global [%0], [%1], 16;" :: "r"(s), "l"(g) : "memory");
}
__device__ __forceinline__ void cp_commit() { asm volatile("cp.async.commit_group;" ::: "memory"); }
__device__ __forceinline__ void cp_wait0()  { asm volatile("cp.async.wait_group 0;" ::: "memory"); }

__device__ __forceinline__ void mma_f16(float4& d, const uint4& a, const uint2& b) {
    asm volatile(
        "mma.sync.aligned.m16n8k16.row.col.f32.f16.f16.f32 "
        "{%0,%1,%2,%3}, {%4,%5,%6,%7}, {%8,%9}, {%0,%1,%2,%3};"
        : "+f"(d.x), "+f"(d.y), "+f"(d.z), "+f"(d.w)
        : "r"(a.x), "r"(a.y), "r"(a.z), "r"(a.w), "r"(b.x), "r"(b.y));
}

// ---------------- kernel 1: NCHW -> NHWC transpose (fp32) ----------------
__global__ void transpose_x_kernel(const float* __restrict__ x)
{
    __shared__ float tile[32][33];
    int bh = blockIdx.z;
    int b = bh >> 6, h = bh & 63;
    int wbase = blockIdx.x * 32;
    int cbase = blockIdx.y * 32;
    int tx = threadIdx.x, ty = threadIdx.y;

    int wi = wbase + tx;
#pragma unroll
    for (int j = 0; j < 4; j++) {
        int c = cbase + ty + j * 8;
        tile[ty + j * 8][tx] = x[((b * CIN + c) * HH + h) * WW + wi];
    }
    __syncthreads();
    int c2 = cbase + tx;
#pragma unroll
    for (int j = 0; j < 4; j++) {
        int w2 = wbase + ty + j * 8;
        g_xt[((bh) * WW + w2) * CIN + c2] = tile[tx][ty + j * 8];
    }
}

// ---------------- kernel 2: pack main weight into fp16 fragment-ordered B tiles ----------------
// half2 word index i: q=i>>12, w=i&4095: r=w&1, lane=(w>>1)&31, ks=(w>>6)&1, n_blk=(w>>7)&31
__global__ void pack_wtB_kernel(const float* __restrict__ weight)
{
    int i = blockIdx.x * blockDim.x + threadIdx.x;
    if (i >= NCHUNK * 4096) return;
    int q = i >> 12;
    int w = i & 4095;
    int r = w & 1;
    int lane = (w >> 1) & 31;
    int ks = (w >> 6) & 1;
    int n_blk = (w >> 7) & 31;
    int tap = q >> 3;
    int n = n_blk * 8 + (lane >> 2);
    int c = (q & 7) * 32 + ks * 16 + (lane & 3) * 2 + r * 8;
    float v0 = weight[(n * CIN + c) * K2 + tap];
    float v1 = weight[(n * CIN + c + 1) * K2 + tap];
    ((__half2*)g_wtB)[i] = __floats2half2_rn(v0, v1);
}

// ---------------- kernel 2b: pack offset+mask weights into fp16 B tiles (N=32 padded) ----------------
__global__ void pack_wtOM_kernel(const float* __restrict__ offset_w,
                                 const float* __restrict__ mod_w)
{
    int i = blockIdx.x * blockDim.x + threadIdx.x;
    if (i >= NCHUNK * 512) return;
    int q = i >> 9;
    int w = i & 511;
    int r = w & 1;
    int lane = (w >> 1) & 31;
    int ks = (w >> 6) & 1;
    int n_blk = (w >> 7) & 3;
    int tap = q >> 3;
    int n = n_blk * 8 + (lane >> 2);
    int c = (q & 7) * 32 + ks * 16 + (lane & 3) * 2 + r * 8;
    float v0 = 0.f, v1 = 0.f;
    if (n < 18)      { v0 = offset_w[(n * CIN + c) * K2 + tap]; v1 = offset_w[(n * CIN + c + 1) * K2 + tap]; }
    else if (n < 27) { v0 = mod_w[((n - 18) * CIN + c) * K2 + tap]; v1 = mod_w[((n - 18) * CIN + c + 1) * K2 + tap]; }
    ((__half2*)g_wtOM)[i] = __floats2half2_rn(v0, v1);
}

// ---------------- kernel 3: offset/mask conv via fp16 mma (A from fp32 x) ----------------
// Block = 1 row (64 px): M=64, N=32, K=2304 in 72 chunks. 256 threads = 8 warps (4M x 2N).
__global__ __launch_bounds__(256) void offmask_mma_kernel(const float* __restrict__ offset_b,
                                                          const float* __restrict__ mod_b)
{
    __shared__ __align__(16) char smA[2][4096];   // A frag: [m_blk4][ks16 2][lane32][16B]
    __shared__ __align__(16) char smB[2][2048];   // B frag: [n_blk4][ks16 2][lane32][8B]

    int t = threadIdx.x;
    int wid = t >> 5, lane = t & 31;
    int bid = blockIdx.x;
    int b = bid >> 6, h = bid & 63;

    uint32_t sbB[2] = { smem_u32(smB[0]), smem_u32(smB[1]) };

    // staging identity: pixel p_=t>>2, channels q4*8..+7
    int p_ = t >> 2, q4 = t & 3;
    int m_blk = p_ >> 4, rr = p_ & 15, rA = rr & 7, r8 = rr >> 3;
    int jw = r8 + 2 * (q4 & 1);
    int ks16s = q4 >> 1;
    int stsBase = ((m_blk * 2 + ks16s) * 32 + 4 * rA) * 4 + jw;   // half2-word index

    int wm = wid & 3, wn = wid >> 2;

    float4 acc[2];
    acc[0] = make_float4(0.f, 0.f, 0.f, 0.f);
    acc[1] = make_float4(0.f, 0.f, 0.f, 0.f);

    float4 ga0, ga1;

    auto loadA = [&](int q) {
        int tap = q >> 3;
        int ki = tap / 3, kj = tap - ki * 3;
        int y = h + ki - 1;
        int xc = p_ + kj - 1;
        if ((unsigned)y < 64u && (unsigned)xc < 64u) {
            const float* src = &g_xt[(((b * HH + y) * WW + xc) * CIN) + (q & 7) * 32 + q4 * 8];
            ga0 = *(const float4*)src;
            ga1 = *(const float4*)(src + 4);
        } else {
            ga0 = make_float4(0.f, 0.f, 0.f, 0.f);
            ga1 = make_float4(0.f, 0.f, 0.f, 0.f);
        }
    };
    auto stsA = [&](int buf) {
        __half2* Aw = (__half2*)smA[buf];
        Aw[stsBase + 0 * 4] = __floats2half2_rn(ga0.x, ga0.y);
        Aw[stsBase + 1 * 4] = __floats2half2_rn(ga0.z, ga0.w);
        Aw[stsBase + 2 * 4] = __floats2half2_rn(ga1.x, ga1.y);
        Aw[stsBase + 3 * 4] = __floats2half2_rn(ga1.z, ga1.w);
    };

    // prologue: stage chunk 0
    loadA(0);
    stsA(0);
    if (t < 128) cp_async16(sbB[0] + t * 16, (const char*)g_wtOM + t * 16);
    cp_commit();
    cp_wait0();
    __syncthreads();

    for (int q = 0; q < NCHUNK; q++) {
        int buf = q & 1, nbuf = buf ^ 1;
        bool pre = (q + 1 < NCHUNK);
        if (pre) {
            loadA(q + 1);
            if (t < 128) cp_async16(sbB[nbuf] + t * 16, (const char*)g_wtOM + (size_t)(q + 1) * 2048 + t * 16);
            cp_commit();
        }

        const uint4* As = (const uint4*)smA[buf];
        const uint2* Bs = (const uint2*)smB[buf];
#pragma unroll
        for (int ks = 0; ks < 2; ks++) {
            uint4 a = As[(wm * 2 + ks) * 32 + lane];
#pragma unroll
            for (int ni = 0; ni < 2; ni++) {
                uint2 bf = Bs[((wn * 2 + ni) * 2 + ks) * 32 + lane];
                mma_f16(acc[ni], a, bf);
            }
        }

        if (pre) stsA(nbuf);
        cp_wait0();
        __syncthreads();
    }

    // epilogue: bias + sigmoid(mask), store fp32
    int r0 = lane >> 2;
#pragma unroll
    for (int ni = 0; ni < 2; ni++) {
        int nb = wn * 16 + ni * 8 + (lane & 3) * 2;
        const float* a4 = (const float*)&acc[ni];
#pragma unroll
        for (int rr2 = 0; rr2 < 2; rr2++) {
            int px = wm * 16 + r0 + rr2 * 8;
#pragma unroll
            for (int cc = 0; cc < 2; cc++) {
                int n = nb + cc;
                if (n >= 27) continue;
                float v = a4[rr2 * 2 + cc];
                if (n < 18) v += offset_b[n];
                else        v = 2.f / (1.f + expf(-(v + mod_b[n - 18])));
                g_offmask[(bid * WW + px) * 32 + n] = v;
            }
        }
    }
}

// ---------------- kernel 4: deformable conv via fp16 mma (A sampled from fp32 x) ----------------
// Block = 2 rows: M=128 px, N=256, K=2304 in 72 chunks of 32. 512 threads = 16 warps (4M x 4N).
// A tile per buffer: 128 rows x 32 k x 2B = 8192 B.  B tile per buffer: 256 n x 32 k x 2B = 16384 B.
#define SM_MIDX   0
#define SM_MWGT   18432
#define SM_A0     36864
#define SM_A1     45056
#define SM_B0     53248
#define SM_B1     69632
#define SM_BIAS   86016
#define SM_TOTAL  87040

__global__ __launch_bounds__(512) void deform_mma_kernel(const float* __restrict__ bias,
                                                         float* __restrict__ out)
{
    extern __shared__ char smem[];
    uint32_t sb = smem_u32(smem);
    int t = threadIdx.x;
    int bid = blockIdx.x;
    int b = bid >> 5, h0 = (bid & 31) << 1;

    int4*   midx  = (int4*)(smem + SM_MIDX);
    float4* mwgt  = (float4*)(smem + SM_MWGT);
    float*  biasS = (float*)(smem + SM_BIAS);

    if (t < 256) biasS[t] = bias[t];

    // ---- per-block sampling metadata: 128 px x 9 taps ----
    for (int e = t; e < 128 * K2; e += 512) {
        int p = e / K2;
        int k = e - p * K2;
        int r = p >> 6, w = p & 63;
        int h = h0 + r;
        const float* om = &g_offmask[(((b * HH + h) * WW) + w) * 32];
        float dy = om[2 * k];
        float dx = om[2 * k + 1];
        float m  = om[18 + k];
        int ki = k / 3, kj = k - ki * 3;
        float py = dy + (float)(h - 1 + ki);
        float px = dx + (float)(w - 1 + kj);
        float y0f = floorf(py), x0f = floorf(px);
        float ly = py - y0f, lx = px - x0f;
        int y0 = (int)y0f, x0 = (int)x0f;
        int y1 = y0 + 1, x1 = x0 + 1;
        float wy0 = 1.f - ly, wx0 = 1.f - lx;
        bool vy0 = (y0 >= 0) && (y0 < HH);
        bool vy1 = (y1 >= 0) && (y1 < HH);
        bool vx0 = (x0 >= 0) && (x0 < WW);
        bool vx1 = (x1 >= 0) && (x1 < WW);
        float w00 = (vy0 && vx0) ? wy0 * wx0 * m : 0.f;
        float w01 = (vy0 && vx1) ? wy0 * lx  * m : 0.f;
        float w10 = (vy1 && vx0) ? ly  * wx0 * m : 0.f;
        float w11 = (vy1 && vx1) ? ly  * lx  * m : 0.f;
        int y0c = min(max(y0, 0), HH - 1);
        int y1c = min(max(y1, 0), HH - 1);
        int x0c = min(max(x0, 0), WW - 1);
        int x1c = min(max(x1, 0), WW - 1);
        midx[e] = make_int4(((b * HH + y0c) * WW + x0c) * CIN,
                            ((b * HH + y0c) * WW + x1c) * CIN,
                            ((b * HH + y1c) * WW + x0c) * CIN,
                            ((b * HH + y1c) * WW + x1c) * CIN);
        mwgt[e] = make_float4(w00, w01, w10, w11);
    }
    __syncthreads();

    // staging identity: pixel p_=t>>2, channels q4*8..+7 of chunk
    int p_ = t >> 2, q4 = t & 3;
    int m_blk = p_ >> 4, rr = p_ & 15, rA = rr & 7, r8 = rr >> 3;
    int jw = r8 + 2 * (q4 & 1);
    int ks16s = q4 >> 1;
    int stsBase = ((m_blk * 2 + ks16s) * 32 + 4 * rA) * 4 + jw;   // half2-word index in A tile

    int wid = t >> 5, lane = t & 31;
    int wm = wid & 3, wn = wid >> 2;

    float4 acc[2][8];
#pragma unroll
    for (int mi = 0; mi < 2; mi++)
#pragma unroll
        for (int ni = 0; ni < 8; ni++) acc[mi][ni] = make_float4(0.f, 0.f, 0.f, 0.f);

    char* Abuf[2] = { smem + SM_A0, smem + SM_A1 };
    char* Bbuf[2] = { smem + SM_B0, smem + SM_B1 };
    uint32_t BbufU[2] = { sb + SM_B0, sb + SM_B1 };

    float4 g0, g1, g2, g3;      // one pass worth of corner values (4 channels, fp32)
    int4 id; float4 wg;

    // combine current pass into 2 half2 words at stsBase + pass*2*4
    auto stsPass = [&](int buf, int pass) {
        float sx = wg.x * g0.x + wg.y * g1.x + wg.z * g2.x + wg.w * g3.x;
        float sy = wg.x * g0.y + wg.y * g1.y + wg.z * g2.y + wg.w * g3.y;
        float sz = wg.x * g0.z + wg.y * g1.z + wg.z * g2.z + wg.w * g3.z;
        float sw = wg.x * g0.w + wg.y * g1.w + wg.z * g2.w + wg.w * g3.w;
        __half2* Aw = (__half2*)Abuf[buf];
        Aw[stsBase + (pass * 2 + 0) * 4] = __floats2half2_rn(sx, sy);
        Aw[stsBase + (pass * 2 + 1) * 4] = __floats2half2_rn(sz, sw);
    };
    auto loadPass = [&](int cb) {
        g0 = *(const float4*)&g_xt[id.x + cb];
        g1 = *(const float4*)&g_xt[id.y + cb];
        g2 = *(const float4*)&g_xt[id.z + cb];
        g3 = *(const float4*)&g_xt[id.w + cb];
    };

    // prologue: stage chunk 0
    {
        id = midx[p_ * K2 + 0];
        wg = mwgt[p_ * K2 + 0];
#pragma unroll
        for (int i = 0; i < 2; i++)
            cp_async16(BbufU[0] + t * 16 + i * 8192, (const char*)g_wtB + t * 16 + i * 8192);
        cp_commit();
        loadPass(q4 * 8);
        stsPass(0, 0);
        loadPass(q4 * 8 + 4);
        stsPass(0, 1);
        cp_wait0();
        __syncthreads();
    }

    for (int q = 0; q < NCHUNK; q++) {
        int buf = q & 1, nbuf = buf ^ 1;
        bool pre = (q + 1 < NCHUNK);

        if (pre) {
            int qq = q + 1;
            int tap = qq >> 3;
            id = midx[p_ * K2 + tap];
            wg = mwgt[p_ * K2 + tap];
            loadPass(((qq & 7) << 5) + q4 * 8);
            const char* bsrc = (const char*)g_wtB + (size_t)qq * 16384;
#pragma unroll
            for (int i = 0; i < 2; i++)
                cp_async16(BbufU[nbuf] + t * 16 + i * 8192, bsrc + t * 16 + i * 8192);
            cp_commit();
        }

        const uint4* As = (const uint4*)Abuf[buf];
        const uint2* Bs = (const uint2*)Bbuf[buf];

        // ks = 0
        {
            uint4 a0 = As[((wm * 2 + 0) * 2 + 0) * 32 + lane];
            uint4 a1 = As[((wm * 2 + 1) * 2 + 0) * 32 + lane];
#pragma unroll
            for (int ni = 0; ni < 8; ni++) {
                uint2 bf = Bs[((wn * 8 + ni) * 2 + 0) * 32 + lane];
                mma_f16(acc[0][ni], a0, bf);
                mma_f16(acc[1][ni], a1, bf);
            }
        }

        // STS pass0 for q+1, load pass1 (overlap with MMA)
        if (pre) {
            stsPass(nbuf, 0);
            loadPass((((q + 1) & 7) << 5) + q4 * 8 + 4);
        }

        // ks = 1
        {
            uint4 a0 = As[((wm * 2 + 0) * 2 + 1) * 32 + lane];
            uint4 a1 = As[((wm * 2 + 1) * 2 + 1) * 32 + lane];
#pragma unroll
            for (int ni = 0; ni < 8; ni++) {
                uint2 bf = Bs[((wn * 8 + ni) * 2 + 1) * 32 + lane];
                mma_f16(acc[0][ni], a0, bf);
                mma_f16(acc[1][ni], a1, bf);
            }
        }

        if (pre) stsPass(nbuf, 1);

        cp_wait0();
        __syncthreads();
    }

    // ---- epilogue: bias + scattered NCHW stores ----
    int gid = lane >> 2, tig = lane & 3;
#pragma unroll
    for (int mi = 0; mi < 2; mi++) {
        int p0 = wm * 32 + mi * 16 + gid;
        int p1 = p0 + 8;
        int h_0 = h0 + (p0 >> 6), w_0 = p0 & 63;
        int h_1 = h0 + (p1 >> 6), w_1 = p1 & 63;
#pragma unroll
        for (int ni = 0; ni < 8; ni++) {
            int o0 = wn * 64 + ni * 8 + tig * 2;
            int o1 = o0 + 1;
            float4 d = acc[mi][ni];
            out[((b * COUT + o0) * HH + h_0) * WW + w_0] = d.x + biasS[o0];
            out[((b * COUT + o1) * HH + h_0) * WW + w_0] = d.y + biasS[o1];
            out[((b * COUT + o0) * HH + h_1) * WW + w_1] = d.z + biasS[o0];
            out[((b * COUT + o1) * HH + h_1) * WW + w_1] = d.w + biasS[o1];
        }
    }
}

// ---------------- launcher ----------------
extern "C" void kernel_launch(void* const* d_in, const int* in_sizes, int n_in,
                              void* d_out, int out_size)
{
    const float* x        = (const float*)d_in[0];
    const float* offset_w = (const float*)d_in[1];
    const float* offset_b = (const float*)d_in[2];
    const float* mod_w    = (const float*)d_in[3];
    const float* mod_b    = (const float*)d_in[4];
    const float* weight   = (const float*)d_in[5];
    const float* bias     = (const float*)d_in[6];
    float* out = (float*)d_out;

    cudaFuncSetAttribute(deform_mma_kernel, cudaFuncAttributeMaxDynamicSharedMemorySize, SM_TOTAL);

    transpose_x_kernel<<<dim3(2, 8, BATCH * HH), dim3(32, 8)>>>(x);
    pack_wtB_kernel<<<(NCHUNK * 4096 + 255) / 256, 256>>>(weight);
    pack_wtOM_kernel<<<(NCHUNK * 512 + 255) / 256, 256>>>(offset_w, mod_w);
    offmask_mma_kernel<<<BATCH * HH, 256>>>(offset_b, mod_b);
    deform_mma_kernel<<<BATCH * HH / 2, 512, SM_TOTAL>>>(bias, out);
}